// round 11
// baseline (speedup 1.0000x reference)
#include <cuda_runtime.h>
#include <math.h>

#define BB 128
#define HH 4
#define NN 4096
#define WW 128
#define CTRL 1560          // H*(3*W+6)
#define EPSF 1e-8f
#define T 1024             // threads per block (32 warps)

__device__ __forceinline__ float softplusf(float x) {
    return (x > 20.f) ? x : log1pf(expf(x));
}
__device__ __forceinline__ float sigmoidf(float x) {
    return 1.f / (1.f + expf(-x));
}

// block-wide reductions over 1024 threads (32 warps)
__device__ __forceinline__ float blockReduceSum32(float v, float* red, int tid) {
    int lane = tid & 31, wid = tid >> 5;
    #pragma unroll
    for (int o = 16; o; o >>= 1) v += __shfl_xor_sync(0xFFFFFFFFu, v, o);
    if (lane == 0) red[wid] = v;
    __syncthreads();
    float r = (tid < 32) ? red[tid] : 0.f;
    if (wid == 0) {
        #pragma unroll
        for (int o = 16; o; o >>= 1) r += __shfl_xor_sync(0xFFFFFFFFu, r, o);
        if (lane == 0) red[0] = r;
    }
    __syncthreads();
    float outv = red[0];
    __syncthreads();
    return outv;
}
__device__ __forceinline__ float blockReduceMax32(float v, float* red, int tid) {
    int lane = tid & 31, wid = tid >> 5;
    #pragma unroll
    for (int o = 16; o; o >>= 1) v = fmaxf(v, __shfl_xor_sync(0xFFFFFFFFu, v, o));
    if (lane == 0) red[wid] = v;
    __syncthreads();
    float r = (tid < 32) ? red[tid] : -INFINITY;
    if (wid == 0) {
        #pragma unroll
        for (int o = 16; o; o >>= 1) r = fmaxf(r, __shfl_xor_sync(0xFFFFFFFFu, r, o));
        if (lane == 0) red[0] = r;
    }
    __syncthreads();
    float outv = red[0];
    __syncthreads();
    return outv;
}

// ============ ONE fused kernel: block b handles batch b end-to-end ==========
__global__ __launch_bounds__(T) void fused_writehead(
    const float* __restrict__ memory,     // [B,N,W]
    const float* __restrict__ controls,   // [B,CTRL]
    const float* __restrict__ bias,       // [H,N]
    float* __restrict__ out)              // [B,N,W]
{
    extern __shared__ float s[];          // [HH*NN] scores -> weights (64 KB)
    __shared__ float kbuf[HH * WW];
    __shared__ float ebuf[HH * WW];
    __shared__ float wbuf[HH * WW];
    __shared__ float red[32];
    __shared__ float kn_s[HH], beta_s[HH], gate_s[HH], gamma_s[HH];
    __shared__ float sh_s[HH][3];

    const int b    = blockIdx.x;
    const int tid  = threadIdx.x;
    const int lane = tid & 31;
    const int warp = tid >> 5;

    // ---------------- prologue: control activations (threads 0..511) -------
    const float* c = controls + b * CTRL;
    if (tid < 512) {
        int h = tid >> 7, w = tid & 127;
        float kv = tanhf(c[h * WW + w]);
        kbuf[tid] = kv;
        ebuf[tid] = sigmoidf(c[512 + h * WW + w]);
        wbuf[tid] = tanhf(c[1024 + h * WW + w]);
        float ss = kv * kv;
        #pragma unroll
        for (int o = 16; o; o >>= 1) ss += __shfl_xor_sync(0xFFFFFFFFu, ss, o);
        if (lane == 0) red[warp] = ss;   // warps 4h..4h+3 hold head h partials
    }
    __syncthreads();
    if (tid < HH) {
        int h4 = tid * 4;
        kn_s[tid]    = sqrtf(red[h4] + red[h4 + 1] + red[h4 + 2] + red[h4 + 3]);
        beta_s[tid]  = softplusf(c[1536 + tid]);
        gate_s[tid]  = sigmoidf(c[1540 + tid]);
        gamma_s[tid] = 1.f + softplusf(c[1556 + tid]);
        float a0 = c[1544 + tid * 3 + 0];
        float a1 = c[1544 + tid * 3 + 1];
        float a2 = c[1544 + tid * 3 + 2];
        float m = fmaxf(a0, fmaxf(a1, a2));
        float e0 = expf(a0 - m), e1 = expf(a1 - m), e2 = expf(a2 - m);
        float inv = 1.f / (e0 + e1 + e2);
        sh_s[tid][0] = e0 * inv; sh_s[tid][1] = e1 * inv; sh_s[tid][2] = e2 * inv;
    }
    __syncthreads();

    const float* memb = memory + (size_t)b * NN * WW;

    // ---------------- pass 1: cosine scores into smem -----------------------
    // 8 lanes/row (16 floats each), 4 rows per warp-group; keys re-read from
    // smem inside the loop to keep register count under the 64-reg cap.
    {
        const int sub  = lane & 7;
        const int rsel = lane >> 3;
        for (int it = 0; it < NN / 128; it++) {      // 32 iterations
            int n = it * 128 + warp * 4 + rsel;
            const float* rp = memb + (size_t)n * WW + sub * 16;
            float4 m0 = *(const float4*)(rp);
            float4 m1 = *(const float4*)(rp + 4);
            float4 m2 = *(const float4*)(rp + 8);
            float4 m3 = *(const float4*)(rp + 12);

            float acc2 =
                  m0.x*m0.x + m0.y*m0.y + m0.z*m0.z + m0.w*m0.w
                + m1.x*m1.x + m1.y*m1.y + m1.z*m1.z + m1.w*m1.w
                + m2.x*m2.x + m2.y*m2.y + m2.z*m2.z + m2.w*m2.w
                + m3.x*m3.x + m3.y*m3.y + m3.z*m3.z + m3.w*m3.w;

            float d[HH];
            #pragma unroll
            for (int h = 0; h < HH; h++) {
                const float4* kp = (const float4*)&kbuf[h * WW + sub * 16];
                float4 k0 = kp[0], k1 = kp[1], k2 = kp[2], k3 = kp[3];
                d[h] = m0.x*k0.x + m0.y*k0.y + m0.z*k0.z + m0.w*k0.w
                     + m1.x*k1.x + m1.y*k1.y + m1.z*k1.z + m1.w*k1.w
                     + m2.x*k2.x + m2.y*k2.y + m2.z*k2.z + m2.w*k2.w
                     + m3.x*k3.x + m3.y*k3.y + m3.z*k3.z + m3.w*k3.w;
            }
            #pragma unroll
            for (int o = 4; o; o >>= 1) {
                acc2 += __shfl_xor_sync(0xFFFFFFFFu, acc2, o);
                d[0] += __shfl_xor_sync(0xFFFFFFFFu, d[0], o);
                d[1] += __shfl_xor_sync(0xFFFFFFFFu, d[1], o);
                d[2] += __shfl_xor_sync(0xFFFFFFFFu, d[2], o);
                d[3] += __shfl_xor_sync(0xFFFFFFFFu, d[3], o);
            }
            if (sub == 0) {
                float nm = sqrtf(acc2);
                s[0 * NN + n] = d[0] / (kn_s[0] * nm + EPSF);
                s[1 * NN + n] = d[1] / (kn_s[1] * nm + EPSF);
                s[2 * NN + n] = d[2] / (kn_s[2] * nm + EPSF);
                s[3 * NN + n] = d[3] / (kn_s[3] * nm + EPSF);
            }
        }
        __syncthreads();
    }

    // ------------- weight pipeline per head (all in smem) -------------------
    for (int h = 0; h < HH; h++) {
        float beta  = beta_s[h];
        float gate  = gate_s[h];
        float gamma = gamma_s[h];
        float s0 = sh_s[h][0], s1 = sh_s[h][1], s2 = sh_s[h][2];
        const float* bp = bias + h * NN;
        float* sh = s + h * NN;

        // prev = softmax(bias[h]) on the fly (bias is batch-independent, L2-hot)
        float bv[4], bmax = -INFINITY;
        #pragma unroll
        for (int k = 0; k < 4; k++) {
            bv[k] = bp[tid + k * T];
            bmax = fmaxf(bmax, bv[k]);
        }
        bmax = blockReduceMax32(bmax, red, tid);
        float bs = 0.f;
        #pragma unroll
        for (int k = 0; k < 4; k++) { bv[k] = __expf(bv[k] - bmax); bs += bv[k]; }
        bs = blockReduceSum32(bs, red, tid);
        float invB = 1.f / bs;

        // softmax(scores*beta)
        float v[4], mx = -INFINITY;
        #pragma unroll
        for (int k = 0; k < 4; k++) {
            v[k] = sh[tid + k * T] * beta;
            mx = fmaxf(mx, v[k]);
        }
        mx = blockReduceMax32(mx, red, tid);
        float sum = 0.f;
        #pragma unroll
        for (int k = 0; k < 4; k++) { v[k] = __expf(v[k] - mx); sum += v[k]; }
        sum = blockReduceSum32(sum, red, tid);
        float invS = 1.f / sum;
        float omg = 1.f - gate;
        #pragma unroll
        for (int k = 0; k < 4; k++) {
            int n = tid + k * T;
            sh[n] = gate * v[k] * invS + omg * bv[k] * invB;   // w_interp
        }
        __syncthreads();

        // circular shift + sharpen + renorm
        float t = 0.f, ws[4];
        #pragma unroll
        for (int k = 0; k < 4; k++) {
            int n = tid + k * T;
            float wsh = s0 * sh[(n - 1) & (NN - 1)] + s1 * sh[n] + s2 * sh[(n + 1) & (NN - 1)];
            float p = exp2f(gamma * __log2f(wsh));   // wsh==0 -> 0, matches fp32 underflow
            ws[k] = p;
            t += p;
        }
        t = blockReduceSum32(t, red, tid);           // internal syncs cover WAR hazard
        float invT = 1.f / (t + EPSF);
        #pragma unroll
        for (int k = 0; k < 4; k++)
            sh[tid + k * T] = ws[k] * invT;          // final write_dist
    }
    __syncthreads();

    // ---------------- pass 2: erase/update/write (reverse order) ------------
    // ea/wa persistent in regs (32); 2-row groups, unroll 2 for load batching.
    {
        float4 ea[HH], wa[HH];
        #pragma unroll
        for (int h = 0; h < HH; h++) {
            ea[h] = *(const float4*)&ebuf[h * WW + lane * 4];
            wa[h] = *(const float4*)&wbuf[h * WW + lane * 4];
        }
        float* outb = out + (size_t)b * NN * WW;
        // warp covers rows [warp*128, warp*128+128), high rows first (L2 recency)
        #pragma unroll 2
        for (int j = 63; j >= 0; j--) {
            int nb = warp * 128 + j * 2;
            float2 wd[HH];
            #pragma unroll
            for (int h = 0; h < HH; h++)
                wd[h] = *(const float2*)&s[h * NN + nb];
            size_t off0 = (size_t)nb * WW + lane * 4;
            float4 m0 = __ldcs((const float4*)(memb + off0));
            float4 m1 = __ldcs((const float4*)(memb + off0 + WW));

            float4 o0, o1;
            o0.x = m0.x * ((1.f - wd[0].x*ea[0].x) * (1.f - wd[1].x*ea[1].x) * (1.f - wd[2].x*ea[2].x) * (1.f - wd[3].x*ea[3].x))
                 + (wd[0].x*wa[0].x + wd[1].x*wa[1].x + wd[2].x*wa[2].x + wd[3].x*wa[3].x);
            o0.y = m0.y * ((1.f - wd[0].x*ea[0].y) * (1.f - wd[1].x*ea[1].y) * (1.f - wd[2].x*ea[2].y) * (1.f - wd[3].x*ea[3].y))
                 + (wd[0].x*wa[0].y + wd[1].x*wa[1].y + wd[2].x*wa[2].y + wd[3].x*wa[3].y);
            o0.z = m0.z * ((1.f - wd[0].x*ea[0].z) * (1.f - wd[1].x*ea[1].z) * (1.f - wd[2].x*ea[2].z) * (1.f - wd[3].x*ea[3].z))
                 + (wd[0].x*wa[0].z + wd[1].x*wa[1].z + wd[2].x*wa[2].z + wd[3].x*wa[3].z);
            o0.w = m0.w * ((1.f - wd[0].x*ea[0].w) * (1.f - wd[1].x*ea[1].w) * (1.f - wd[2].x*ea[2].w) * (1.f - wd[3].x*ea[3].w))
                 + (wd[0].x*wa[0].w + wd[1].x*wa[1].w + wd[2].x*wa[2].w + wd[3].x*wa[3].w);

            o1.x = m1.x * ((1.f - wd[0].y*ea[0].x) * (1.f - wd[1].y*ea[1].x) * (1.f - wd[2].y*ea[2].x) * (1.f - wd[3].y*ea[3].x))
                 + (wd[0].y*wa[0].x + wd[1].y*wa[1].x + wd[2].y*wa[2].x + wd[3].y*wa[3].x);
            o1.y = m1.y * ((1.f - wd[0].y*ea[0].y) * (1.f - wd[1].y*ea[1].y) * (1.f - wd[2].y*ea[2].y) * (1.f - wd[3].y*ea[3].y))
                 + (wd[0].y*wa[0].y + wd[1].y*wa[1].y + wd[2].y*wa[2].y + wd[3].y*wa[3].y);
            o1.z = m1.z * ((1.f - wd[0].y*ea[0].z) * (1.f - wd[1].y*ea[1].z) * (1.f - wd[2].y*ea[2].z) * (1.f - wd[3].y*ea[3].z))
                 + (wd[0].y*wa[0].z + wd[1].y*wa[1].z + wd[2].y*wa[2].z + wd[3].y*wa[3].z);
            o1.w = m1.w * ((1.f - wd[0].y*ea[0].w) * (1.f - wd[1].y*ea[1].w) * (1.f - wd[2].y*ea[2].w) * (1.f - wd[3].y*ea[3].w))
                 + (wd[0].y*wa[0].w + wd[1].y*wa[1].w + wd[2].y*wa[2].w + wd[3].y*wa[3].w);

            __stcs((float4*)(outb + off0), o0);
            __stcs((float4*)(outb + off0 + WW), o1);
        }
    }
}

// ---------------------------------------------------------------------------
extern "C" void kernel_launch(void* const* d_in, const int* in_sizes, int n_in,
                              void* d_out, int out_size) {
    const float* memory   = (const float*)d_in[0];   // [B,N,W]
    const float* controls = (const float*)d_in[1];   // [B,CTRL]
    const float* bias     = (const float*)d_in[2];   // [1,H,N]
    float* out = (float*)d_out;                      // [B,N,W]

    const int smem = HH * NN * sizeof(float);        // 64 KB dynamic
    cudaFuncSetAttribute(fused_writehead,
                         cudaFuncAttributeMaxDynamicSharedMemorySize, smem);
    fused_writehead<<<BB, T, smem>>>(memory, controls, bias, out);
}

// round 13
// speedup vs baseline: 1.3786x; 1.3786x over previous
#include <cuda_runtime.h>
#include <math.h>

#define BB 128
#define HH 4
#define NN 4096
#define WW 128
#define CTRL 1560          // H*(3*W+6)
#define EPSF 1e-8f
#define T 512              // threads per block (16 warps)

__device__ __forceinline__ float softplusf(float x) {
    return (x > 20.f) ? x : log1pf(expf(x));
}
__device__ __forceinline__ float sigmoidf(float x) {
    return 1.f / (1.f + expf(-x));
}

// block-wide reductions over 512 threads (16 warps)
__device__ __forceinline__ float blockReduceSum16(float v, float* red, int tid) {
    int lane = tid & 31, wid = tid >> 5;
    #pragma unroll
    for (int o = 16; o; o >>= 1) v += __shfl_xor_sync(0xFFFFFFFFu, v, o);
    if (lane == 0) red[wid] = v;
    __syncthreads();
    float r = (tid < 16) ? red[tid] : 0.f;
    if (wid == 0) {
        #pragma unroll
        for (int o = 16; o; o >>= 1) r += __shfl_xor_sync(0xFFFFFFFFu, r, o);
        if (lane == 0) red[0] = r;
    }
    __syncthreads();
    float outv = red[0];
    __syncthreads();
    return outv;
}
__device__ __forceinline__ float blockReduceMax16(float v, float* red, int tid) {
    int lane = tid & 31, wid = tid >> 5;
    #pragma unroll
    for (int o = 16; o; o >>= 1) v = fmaxf(v, __shfl_xor_sync(0xFFFFFFFFu, v, o));
    if (lane == 0) red[wid] = v;
    __syncthreads();
    float r = (tid < 16) ? red[tid] : -INFINITY;
    if (wid == 0) {
        #pragma unroll
        for (int o = 16; o; o >>= 1) r = fmaxf(r, __shfl_xor_sync(0xFFFFFFFFu, r, o));
        if (lane == 0) red[0] = r;
    }
    __syncthreads();
    float outv = red[0];
    __syncthreads();
    return outv;
}

// ============ ONE fused kernel: block b handles batch b end-to-end ==========
__global__ __launch_bounds__(T) void fused_writehead(
    const float* __restrict__ memory,     // [B,N,W]
    const float* __restrict__ controls,   // [B,CTRL]
    const float* __restrict__ bias,       // [H,N]
    float* __restrict__ out)              // [B,N,W]
{
    extern __shared__ float s[];          // [HH*NN] scores -> weights (64 KB)
    __shared__ float kbuf[HH * WW];
    __shared__ float ebuf[HH * WW];
    __shared__ float wbuf[HH * WW];
    __shared__ float red[16];
    __shared__ float kn_s[HH], beta_s[HH], gate_s[HH], gamma_s[HH];
    __shared__ float sh_s[HH][3];

    const int b    = blockIdx.x;
    const int tid  = threadIdx.x;
    const int lane = tid & 31;
    const int warp = tid >> 5;

    // ---------------- prologue: control activations (1 value/thread) -------
    {
        const float* c = controls + b * CTRL;
        int h = tid >> 7, w = tid & 127;
        float kv = tanhf(c[h * WW + w]);
        kbuf[tid] = kv;
        ebuf[tid] = sigmoidf(c[512 + h * WW + w]);
        wbuf[tid] = tanhf(c[1024 + h * WW + w]);

        float ss = kv * kv;
        #pragma unroll
        for (int o = 16; o; o >>= 1) ss += __shfl_xor_sync(0xFFFFFFFFu, ss, o);
        if (lane == 0) red[warp] = ss;   // warps 4h..4h+3 hold head h partials
        __syncthreads();
        if (tid < HH) {
            int h4 = tid * 4;
            kn_s[tid]    = sqrtf(red[h4] + red[h4 + 1] + red[h4 + 2] + red[h4 + 3]);
            beta_s[tid]  = softplusf(c[1536 + tid]);
            gate_s[tid]  = sigmoidf(c[1540 + tid]);
            gamma_s[tid] = 1.f + softplusf(c[1556 + tid]);
            float a0 = c[1544 + tid * 3 + 0];
            float a1 = c[1544 + tid * 3 + 1];
            float a2 = c[1544 + tid * 3 + 2];
            float m = fmaxf(a0, fmaxf(a1, a2));
            float e0 = expf(a0 - m), e1 = expf(a1 - m), e2 = expf(a2 - m);
            float inv = 1.f / (e0 + e1 + e2);
            sh_s[tid][0] = e0 * inv; sh_s[tid][1] = e1 * inv; sh_s[tid][2] = e2 * inv;
        }
        __syncthreads();
    }

    const float* memb = memory + (size_t)b * NN * WW;

    // ---------------- pass 1: cosine scores into smem -----------------------
    // 8 lanes/row (16 floats each); TWO 4-row groups per iteration with all
    // 8 LDG.128 issued up front (MLP_eff ~ 8) before any reduction.
    {
        const int sub  = lane & 7;
        const int rsel = lane >> 3;
        float4 kk[HH][4];
        float  kn[HH];
        #pragma unroll
        for (int h = 0; h < HH; h++) {
            const float* kp = &kbuf[h * WW + sub * 16];
            #pragma unroll
            for (int i = 0; i < 4; i++) kk[h][i] = *(const float4*)(kp + 4 * i);
            kn[h] = kn_s[h];
        }
        for (int it = 0; it < 64; it += 2) {
            int nA = it * 64 + warp * 4 + rsel;
            int nB = nA + 64;
            const float* rpA = memb + (size_t)nA * WW + sub * 16;
            const float* rpB = memb + (size_t)nB * WW + sub * 16;
            float4 a[4], bb[4];
            #pragma unroll
            for (int i = 0; i < 4; i++) a[i]  = *(const float4*)(rpA + 4 * i);
            #pragma unroll
            for (int i = 0; i < 4; i++) bb[i] = *(const float4*)(rpB + 4 * i);

            // ---- group A ----
            {
                float m2 = 0.f, d0 = 0.f, d1 = 0.f, d2 = 0.f, d3 = 0.f;
                #pragma unroll
                for (int i = 0; i < 4; i++) {
                    m2 = fmaf(a[i].x, a[i].x, fmaf(a[i].y, a[i].y, fmaf(a[i].z, a[i].z, fmaf(a[i].w, a[i].w, m2))));
                    d0 = fmaf(a[i].x, kk[0][i].x, fmaf(a[i].y, kk[0][i].y, fmaf(a[i].z, kk[0][i].z, fmaf(a[i].w, kk[0][i].w, d0))));
                    d1 = fmaf(a[i].x, kk[1][i].x, fmaf(a[i].y, kk[1][i].y, fmaf(a[i].z, kk[1][i].z, fmaf(a[i].w, kk[1][i].w, d1))));
                    d2 = fmaf(a[i].x, kk[2][i].x, fmaf(a[i].y, kk[2][i].y, fmaf(a[i].z, kk[2][i].z, fmaf(a[i].w, kk[2][i].w, d2))));
                    d3 = fmaf(a[i].x, kk[3][i].x, fmaf(a[i].y, kk[3][i].y, fmaf(a[i].z, kk[3][i].z, fmaf(a[i].w, kk[3][i].w, d3))));
                }
                #pragma unroll
                for (int o = 4; o; o >>= 1) {
                    m2 += __shfl_xor_sync(0xFFFFFFFFu, m2, o);
                    d0 += __shfl_xor_sync(0xFFFFFFFFu, d0, o);
                    d1 += __shfl_xor_sync(0xFFFFFFFFu, d1, o);
                    d2 += __shfl_xor_sync(0xFFFFFFFFu, d2, o);
                    d3 += __shfl_xor_sync(0xFFFFFFFFu, d3, o);
                }
                if (sub == 0) {
                    float nm = sqrtf(m2);
                    s[0 * NN + nA] = d0 / (kn[0] * nm + EPSF);
                    s[1 * NN + nA] = d1 / (kn[1] * nm + EPSF);
                    s[2 * NN + nA] = d2 / (kn[2] * nm + EPSF);
                    s[3 * NN + nA] = d3 / (kn[3] * nm + EPSF);
                }
            }
            // ---- group B ----
            {
                float m2 = 0.f, d0 = 0.f, d1 = 0.f, d2 = 0.f, d3 = 0.f;
                #pragma unroll
                for (int i = 0; i < 4; i++) {
                    m2 = fmaf(bb[i].x, bb[i].x, fmaf(bb[i].y, bb[i].y, fmaf(bb[i].z, bb[i].z, fmaf(bb[i].w, bb[i].w, m2))));
                    d0 = fmaf(bb[i].x, kk[0][i].x, fmaf(bb[i].y, kk[0][i].y, fmaf(bb[i].z, kk[0][i].z, fmaf(bb[i].w, kk[0][i].w, d0))));
                    d1 = fmaf(bb[i].x, kk[1][i].x, fmaf(bb[i].y, kk[1][i].y, fmaf(bb[i].z, kk[1][i].z, fmaf(bb[i].w, kk[1][i].w, d1))));
                    d2 = fmaf(bb[i].x, kk[2][i].x, fmaf(bb[i].y, kk[2][i].y, fmaf(bb[i].z, kk[2][i].z, fmaf(bb[i].w, kk[2][i].w, d2))));
                    d3 = fmaf(bb[i].x, kk[3][i].x, fmaf(bb[i].y, kk[3][i].y, fmaf(bb[i].z, kk[3][i].z, fmaf(bb[i].w, kk[3][i].w, d3))));
                }
                #pragma unroll
                for (int o = 4; o; o >>= 1) {
                    m2 += __shfl_xor_sync(0xFFFFFFFFu, m2, o);
                    d0 += __shfl_xor_sync(0xFFFFFFFFu, d0, o);
                    d1 += __shfl_xor_sync(0xFFFFFFFFu, d1, o);
                    d2 += __shfl_xor_sync(0xFFFFFFFFu, d2, o);
                    d3 += __shfl_xor_sync(0xFFFFFFFFu, d3, o);
                }
                if (sub == 0) {
                    float nm = sqrtf(m2);
                    s[0 * NN + nB] = d0 / (kn[0] * nm + EPSF);
                    s[1 * NN + nB] = d1 / (kn[1] * nm + EPSF);
                    s[2 * NN + nB] = d2 / (kn[2] * nm + EPSF);
                    s[3 * NN + nB] = d3 / (kn[3] * nm + EPSF);
                }
            }
        }
        __syncthreads();
    }

    // ------------- weight pipeline per head (all in smem) -------------------
    for (int h = 0; h < HH; h++) {
        float beta  = beta_s[h];
        float gate  = gate_s[h];
        float gamma = gamma_s[h];
        float s0 = sh_s[h][0], s1 = sh_s[h][1], s2 = sh_s[h][2];
        const float* bp = bias + h * NN;
        float* sh = s + h * NN;

        // prev = softmax(bias[h]) computed on the fly
        float bv[8], bmax = -INFINITY;
        #pragma unroll
        for (int k = 0; k < 8; k++) {
            bv[k] = bp[tid + k * T];
            bmax = fmaxf(bmax, bv[k]);
        }
        bmax = blockReduceMax16(bmax, red, tid);
        float bs = 0.f;
        #pragma unroll
        for (int k = 0; k < 8; k++) { bv[k] = __expf(bv[k] - bmax); bs += bv[k]; }
        bs = blockReduceSum16(bs, red, tid);
        float invB = 1.f / bs;

        // softmax(scores*beta)
        float v[8], mx = -INFINITY;
        #pragma unroll
        for (int k = 0; k < 8; k++) {
            v[k] = sh[tid + k * T] * beta;
            mx = fmaxf(mx, v[k]);
        }
        mx = blockReduceMax16(mx, red, tid);
        float sum = 0.f;
        #pragma unroll
        for (int k = 0; k < 8; k++) { v[k] = __expf(v[k] - mx); sum += v[k]; }
        sum = blockReduceSum16(sum, red, tid);
        float invS = 1.f / sum;
        float omg = 1.f - gate;
        #pragma unroll
        for (int k = 0; k < 8; k++) {
            int n = tid + k * T;
            sh[n] = gate * v[k] * invS + omg * bv[k] * invB;   // w_interp
        }
        __syncthreads();

        // circular shift + sharpen + renorm
        float t = 0.f, ws[8];
        #pragma unroll
        for (int k = 0; k < 8; k++) {
            int n = tid + k * T;
            float wsh = s0 * sh[(n - 1) & (NN - 1)] + s1 * sh[n] + s2 * sh[(n + 1) & (NN - 1)];
            float p = exp2f(gamma * __log2f(wsh));   // wsh==0 -> 0, matches fp32 underflow
            ws[k] = p;
            t += p;
        }
        t = blockReduceSum16(t, red, tid);           // internal syncs cover WAR hazard
        float invT = 1.f / (t + EPSF);
        #pragma unroll
        for (int k = 0; k < 8; k++)
            sh[tid + k * T] = ws[k] * invT;          // final write_dist
    }
    __syncthreads();

    // ---------------- pass 2: erase/update/write (8-row groups) -------------
    {
        float4 ea[HH], wa[HH];
        #pragma unroll
        for (int h = 0; h < HH; h++) {
            ea[h] = *(const float4*)&ebuf[h * WW + lane * 4];
            wa[h] = *(const float4*)&wbuf[h * WW + lane * 4];
        }
        float* outb = out + (size_t)b * NN * WW;
        // warp covers rows [warp*256, warp*256+256), 8 rows/iter, high first
        for (int j = 31; j >= 0; j--) {
            int nb = warp * 256 + j * 8;
            // front-batch: 8 row loads + per-head wd vectors
            float4 m[8];
            float4 wv0[HH], wv1[HH];           // wd for rows 0-3 / 4-7
            #pragma unroll
            for (int r = 0; r < 8; r++) {
                size_t off = (size_t)(nb + r) * WW + lane * 4;
                m[r] = __ldcs((const float4*)(memb + off));
            }
            #pragma unroll
            for (int h = 0; h < HH; h++) {
                wv0[h] = *(const float4*)&s[h * NN + nb];
                wv1[h] = *(const float4*)&s[h * NN + nb + 4];
            }
            #pragma unroll
            for (int r = 0; r < 8; r++) {
                float w0, w1, w2, w3;
                if (r < 4) {
                    w0 = (&wv0[0].x)[r]; w1 = (&wv0[1].x)[r];
                    w2 = (&wv0[2].x)[r]; w3 = (&wv0[3].x)[r];
                } else {
                    w0 = (&wv1[0].x)[r - 4]; w1 = (&wv1[1].x)[r - 4];
                    w2 = (&wv1[2].x)[r - 4]; w3 = (&wv1[3].x)[r - 4];
                }
                float4 o;
                o.x = m[r].x * ((1.f - w0*ea[0].x) * (1.f - w1*ea[1].x) * (1.f - w2*ea[2].x) * (1.f - w3*ea[3].x))
                    + (w0*wa[0].x + w1*wa[1].x + w2*wa[2].x + w3*wa[3].x);
                o.y = m[r].y * ((1.f - w0*ea[0].y) * (1.f - w1*ea[1].y) * (1.f - w2*ea[2].y) * (1.f - w3*ea[3].y))
                    + (w0*wa[0].y + w1*wa[1].y + w2*wa[2].y + w3*wa[3].y);
                o.z = m[r].z * ((1.f - w0*ea[0].z) * (1.f - w1*ea[1].z) * (1.f - w2*ea[2].z) * (1.f - w3*ea[3].z))
                    + (w0*wa[0].z + w1*wa[1].z + w2*wa[2].z + w3*wa[3].z);
                o.w = m[r].w * ((1.f - w0*ea[0].w) * (1.f - w1*ea[1].w) * (1.f - w2*ea[2].w) * (1.f - w3*ea[3].w))
                    + (w0*wa[0].w + w1*wa[1].w + w2*wa[2].w + w3*wa[3].w);
                size_t off = (size_t)(nb + r) * WW + lane * 4;
                __stcs((float4*)(outb + off), o);
            }
        }
    }
}

// ---------------------------------------------------------------------------
extern "C" void kernel_launch(void* const* d_in, const int* in_sizes, int n_in,
                              void* d_out, int out_size) {
    const float* memory   = (const float*)d_in[0];   // [B,N,W]
    const float* controls = (const float*)d_in[1];   // [B,CTRL]
    const float* bias     = (const float*)d_in[2];   // [1,H,N]
    float* out = (float*)d_out;                      // [B,N,W]

    const int smem = HH * NN * sizeof(float);        // 64 KB dynamic
    cudaFuncSetAttribute(fused_writehead,
                         cudaFuncAttributeMaxDynamicSharedMemorySize, smem);
    fused_writehead<<<BB, T, smem>>>(memory, controls, bias, out);
}